// round 6
// baseline (speedup 1.0000x reference)
#include <cuda_runtime.h>
#include <cuda_bf16.h>

#define NU      50001
#define NI      100001
#define NN      150002
#define DD      64
#define NE      2000000
#define BATCHSZ 2048
#define EPSF    1e-9f
#define GAMMAF  1e-10f
#define INIT_BLOCKS 9376   // ceil(NN*DD/4 / 256)

// ---------------- static scratch ----------------
__device__ __align__(128) float g_total[2][(size_t)NN * DD]; // ping-pong, 76.8 MB
__device__ int   g_cnt[2 * NN];
__device__ int   g_off[2 * (NN + 1)];
__device__ int   g_cur[2 * NN];
__device__ int   g_csrc[2 * NE];                             // CSR: src per slot
__device__ float g_ns[2 * NN];                               // 1/(den+eps)  (== norm)
__device__ float g_rs[2 * NN];                               // old_scale/(den+eps)
__device__ float g_bpr[2 * BATCHSZ];
__device__ float g_squ[INIT_BLOCKS];
__device__ float g_sqi[INIT_BLOCKS];

// ---------------------------------------------------------------------------
// 1) total[0] = concat(user, item); per-block sum-of-squares partials
// ---------------------------------------------------------------------------
__global__ __launch_bounds__(256) void init_kernel(const float4* __restrict__ ue,
                                                   const float4* __restrict__ ie) {
    __shared__ float shu[256], shi[256];
    int i = blockIdx.x * 256 + threadIdx.x;
    const int tot4 = NN * DD / 4;
    const int nu4  = NU * DD / 4;
    float su = 0.f, si = 0.f;
    if (i < tot4) {
        float4 v;
        if (i < nu4) { v = ue[i]; su = v.x*v.x + v.y*v.y + v.z*v.z + v.w*v.w; }
        else         { v = ie[i - nu4]; si = v.x*v.x + v.y*v.y + v.z*v.z + v.w*v.w; }
        ((float4*)g_total[0])[i] = v;
    }
    shu[threadIdx.x] = su; shi[threadIdx.x] = si;
    __syncthreads();
    for (int s = 128; s; s >>= 1) {
        if (threadIdx.x < s) {
            shu[threadIdx.x] += shu[threadIdx.x + s];
            shi[threadIdx.x] += shi[threadIdx.x + s];
        }
        __syncthreads();
    }
    if (threadIdx.x == 0) { g_squ[blockIdx.x] = shu[0]; g_sqi[blockIdx.x] = shi[0]; }
}

// ---------------------------------------------------------------------------
// 2) per-node norms for both behaviors + zero counters
// ---------------------------------------------------------------------------
__global__ __launch_bounds__(256) void norm_kernel(const float* __restrict__ oldd,
                                                   const float* __restrict__ nowd,
                                                   const float* __restrict__ dwp,
                                                   const float* __restrict__ owp) {
    int i = blockIdx.x * 256 + threadIdx.x;    // over [0, 2*NN)
    if (i >= 2 * NN) return;
    float dw = __ldg(dwp), ow = __ldg(owp);
    float od = __ldg(oldd + i), nd = __ldg(nowd + i);
    float den = sqrtf(fmaxf(od * dw, 0.f) + nd);
    float inv = 1.f / (den + EPSF);
    g_ns[i] = inv;
    g_rs[i] = sqrtf(fmaxf(od * ow, 0.f)) * inv;
    g_cnt[i] = 0;
}

// ---------------------------------------------------------------------------
// 3) histogram over dst (both behaviors)
// ---------------------------------------------------------------------------
__global__ __launch_bounds__(256) void hist_kernel(const int* __restrict__ dst_all) {
    int i = blockIdx.x * 256 + threadIdx.x;
    if (i >= 2 * NE) return;
    int b = (i >= NE);
    int d = __ldg(dst_all + i);
    atomicAdd(&g_cnt[b * NN + d], 1);
}

// ---------------------------------------------------------------------------
// 4) exclusive scan (one block of 1024 threads per behavior)
// ---------------------------------------------------------------------------
__global__ __launch_bounds__(1024) void scan_kernel() {
    int b = blockIdx.x;
    int tid = threadIdx.x, lane = tid & 31, wid = tid >> 5;
    __shared__ int wsum[32];
    __shared__ int stot;
    int carry = 0;
    const int* cnt = g_cnt + b * NN;
    int* off = g_off + b * (NN + 1);
    int* cur = g_cur + b * NN;
    for (int base = 0; base < NN; base += 4096) {
        int i0 = base + tid * 4;
        int v0 = (i0 + 0 < NN) ? cnt[i0 + 0] : 0;
        int v1 = (i0 + 1 < NN) ? cnt[i0 + 1] : 0;
        int v2 = (i0 + 2 < NN) ? cnt[i0 + 2] : 0;
        int v3 = (i0 + 3 < NN) ? cnt[i0 + 3] : 0;
        int ts = v0 + v1 + v2 + v3;
        int x = ts;
        #pragma unroll
        for (int o = 1; o < 32; o <<= 1) { int y = __shfl_up_sync(~0u, x, o); if (lane >= o) x += y; }
        if (lane == 31) wsum[wid] = x;
        __syncthreads();
        if (wid == 0) {
            int w = wsum[lane];
            #pragma unroll
            for (int o = 1; o < 32; o <<= 1) { int y = __shfl_up_sync(~0u, w, o); if (lane >= o) w += y; }
            wsum[lane] = w;
            if (lane == 31) stot = w;
        }
        __syncthreads();
        int excl = carry + (x - ts) + (wid ? wsum[wid - 1] : 0);
        if (i0 + 0 < NN) { off[i0 + 0] = excl; cur[i0 + 0] = excl; } excl += v0;
        if (i0 + 1 < NN) { off[i0 + 1] = excl; cur[i0 + 1] = excl; } excl += v1;
        if (i0 + 2 < NN) { off[i0 + 2] = excl; cur[i0 + 2] = excl; } excl += v2;
        if (i0 + 3 < NN) { off[i0 + 3] = excl; cur[i0 + 3] = excl; }
        carry += stot;
        __syncthreads();
    }
    if (tid == 0) off[NN] = carry;
}

// ---------------------------------------------------------------------------
// 5) CSR fill (both behaviors)
// ---------------------------------------------------------------------------
__global__ __launch_bounds__(256) void fill_kernel(const int* __restrict__ src_all,
                                                   const int* __restrict__ dst_all) {
    int i = blockIdx.x * 256 + threadIdx.x;
    if (i >= 2 * NE) return;
    int b = (i >= NE);
    int d = __ldg(dst_all + i);
    int s = __ldg(src_all + i);
    int pos = atomicAdd(&g_cur[b * NN + d], 1);
    g_csrc[b * NE + pos] = s;
}

// ---------------------------------------------------------------------------
// 6) fused gather + combine: one warp per node.
//    reads g_total[p], writes g_total[1-p].  (p resolved in DEVICE code)
// ---------------------------------------------------------------------------
__global__ __launch_bounds__(256) void gathcomb_kernel(
    const float* __restrict__ ls,     // last_stage[b] : [2][NN][DD]
    const float* __restrict__ cw,     // conv_w[b] : 4 floats
    int b, int p)
{
    int node = blockIdx.x * 8 + (threadIdx.x >> 5);
    if (node >= NN) return;
    int lane = threadIdx.x & 31;

    const float* tot_in  = g_total[p];
    float*       tot_out = g_total[1 - p];
    const int*   csrc    = g_csrc + (size_t)b * NE;
    const float* nsb     = g_ns + b * NN;

    int r0 = __ldg(g_off + b * (NN + 1) + node);
    int r1 = __ldg(g_off + b * (NN + 1) + node + 1);
    int cnt = r1 - r0;

    float ax = 0.f, ay = 0.f;
    for (int base = 0; base < cnt; base += 32) {
        int myidx = -1;
        if (base + lane < cnt) myidx = __ldg(csrc + r0 + base + lane);
        int m = min(32, cnt - base);
        #pragma unroll 4
        for (int k = 0; k < m; k++) {
            int s = __shfl_sync(0xffffffffu, myidx, k);
            float ns = __ldg(nsb + s);
            float2 v = *(const float2*)(tot_in + (size_t)s * DD + lane * 2);
            ax = fmaf(ns, v.x, ax);
            ay = fmaf(ns, v.y, ay);
        }
    }

    float inv = __ldg(g_ns + b * NN + node);
    float rs  = __ldg(g_rs + b * NN + node);
    float c00 = __ldg(cw + 0), c01 = __ldg(cw + 1);
    float c10 = __ldg(cw + 2), c11 = __ldg(cw + 3);

    size_t base2 = (size_t)node * DD + lane * 2;
    float2 t  = *(const float2*)(tot_in + base2);
    float2 l0 = *(const float2*)(ls + base2);
    float2 l1 = *(const float2*)(ls + (size_t)NN * DD + base2);

    float e1x = inv * ax, e1y = inv * ay;
    float mx = (t.x + (c00 * l0.x * rs + c01 * t.x) + (c10 * l1.x * rs + c11 * e1x)) * (1.f / 3.f);
    float my = (t.y + (c00 * l0.y * rs + c01 * t.y) + (c10 * l1.y * rs + c11 * e1y)) * (1.f / 3.f);

    float sq = mx * mx + my * my;
    #pragma unroll
    for (int o = 16; o; o >>= 1) sq += __shfl_xor_sync(0xffffffffu, sq, o);
    float rn = 1.f / fmaxf(sqrtf(sq), 1e-12f);

    float2 outv = make_float2(t.x + mx * rn, t.y + my * rn);
    *(float2*)(tot_out + base2) = outv;
}

// ---------------------------------------------------------------------------
// 7) BPR loss (one warp per sample). `which` selects the ping-pong buffer
//    holding the post-update embeddings for behavior b — resolved on DEVICE.
// ---------------------------------------------------------------------------
__global__ __launch_bounds__(256) void loss_kernel(const int* __restrict__ bdata,
                                                   int b, int which) {
    int w = (blockIdx.x * blockDim.x + threadIdx.x) >> 5;
    if (w >= BATCHSZ) return;
    int lane = threadIdx.x & 31;

    const float* emb = g_total[which];   // DEVICE-side symbol resolution

    const int* r = bdata + (size_t)w * 6 + (size_t)b * 3;  // (BATCH, 2, 3)
    int u  = __ldg(r + 0);
    int pi = NU + __ldg(r + 1);
    int ni = NU + __ldg(r + 2);

    float2 uv = *(const float2*)(emb + (size_t)u  * DD + lane * 2);
    float2 pv = *(const float2*)(emb + (size_t)pi * DD + lane * 2);
    float2 nv = *(const float2*)(emb + (size_t)ni * DD + lane * 2);

    float s0 = uv.x * pv.x + uv.y * pv.y;
    float s1 = uv.x * nv.x + uv.y * nv.y;
    #pragma unroll
    for (int o = 16; o; o >>= 1) {
        s0 += __shfl_xor_sync(0xffffffffu, s0, o);
        s1 += __shfl_xor_sync(0xffffffffu, s1, o);
    }
    if (lane == 0) {
        float diff = s0 - s1;
        float sig  = 1.f / (1.f + expf(-diff));
        g_bpr[b * BATCHSZ + w] = -logf(GAMMAF + sig);
    }
}

// ---------------------------------------------------------------------------
// 8) final deterministic reduction -> out[0]
// ---------------------------------------------------------------------------
__global__ __launch_bounds__(1024) void final_kernel(float* __restrict__ out) {
    __shared__ float sh[1024];
    int t = threadIdx.x;

    float a = 0.f;
    for (int i = t; i < 2 * BATCHSZ; i += 1024) a += g_bpr[i];
    float su = 0.f, si = 0.f;
    for (int i = t; i < INIT_BLOCKS; i += 1024) { su += g_squ[i]; si += g_sqi[i]; }

    float res[3] = {a, su, si};
    float red[3];
    #pragma unroll
    for (int k = 0; k < 3; k++) {
        sh[t] = res[k];
        __syncthreads();
        for (int s = 512; s; s >>= 1) {
            if (t < s) sh[t] += sh[t + s];
            __syncthreads();
        }
        red[k] = sh[0];
        __syncthreads();
    }

    if (t == 0) {
        float total_loss = red[0] * (1.f / BATCHSZ);
        float emb_loss   = (sqrtf(red[1]) + sqrtf(red[2])) / (float)NI;
        out[0] = total_loss + 1e-4f * emb_loss;
    }
}

// ---------------------------------------------------------------------------
extern "C" void kernel_launch(void* const* d_in, const int* in_sizes, int n_in,
                              void* d_out, int out_size) {
    const float* ue    = (const float*)d_in[0];
    const float* ie    = (const float*)d_in[1];
    const float* nowd  = (const float*)d_in[2];
    const float* oldd  = (const float*)d_in[3];
    const float* ls    = (const float*)d_in[4];
    const float* dw    = (const float*)d_in[5];
    const float* ow    = (const float*)d_in[6];
    const float* cw    = (const float*)d_in[7];
    const int*   src   = (const int*)d_in[8];
    const int*   dst   = (const int*)d_in[9];
    const int*   bdata = (const int*)d_in[10];
    float*       out   = (float*)d_out;

    init_kernel<<<INIT_BLOCKS, 256>>>((const float4*)ue, (const float4*)ie);
    norm_kernel<<<(2 * NN + 255) / 256, 256>>>(oldd, nowd, dw, ow);
    hist_kernel<<<(2 * NE + 255) / 256, 256>>>(dst);
    scan_kernel<<<2, 1024>>>();
    fill_kernel<<<(2 * NE + 255) / 256, 256>>>(src, dst);

    // behavior 0: read buf0 -> write buf1 ; behavior 1: read buf1 -> write buf0
    gathcomb_kernel<<<(NN + 7) / 8, 256>>>(ls, cw + 0, 0, 0);
    loss_kernel<<<(BATCHSZ * 32 + 255) / 256, 256>>>(bdata, 0, 1);
    gathcomb_kernel<<<(NN + 7) / 8, 256>>>(ls + (size_t)2 * NN * DD, cw + 4, 1, 1);
    loss_kernel<<<(BATCHSZ * 32 + 255) / 256, 256>>>(bdata, 1, 0);

    final_kernel<<<1, 1024>>>(out);
}

// round 7
// speedup vs baseline: 1.3108x; 1.3108x over previous
#include <cuda_runtime.h>
#include <cuda_bf16.h>

#define NU      50001
#define NI      100001
#define NN      150002
#define DD      64
#define NE      2000000
#define BATCHSZ 2048
#define EPSF    1e-9f
#define GAMMAF  1e-10f
#define INIT_BLOCKS 9376   // ceil(NN*DD/4 / 256)
#define SCHUNK  4096
#define SNB     37         // ceil(NN / SCHUNK)

// ---------------- static scratch ----------------
__device__ __align__(128) float g_total[2][(size_t)NN * DD]; // ping-pong, 76.8 MB
__device__ int   g_cnt[2 * NN];
__device__ int   g_off[2 * (NN + 1)];
__device__ int   g_cur[2 * NN];
__device__ int   g_csrc[2 * NE];                             // CSR: src per slot
__device__ float g_ns[2 * NN];                               // 1/(den+eps)  (== norm)
__device__ float g_rs[2 * NN];                               // old_scale/(den+eps)
__device__ float g_bpr[2 * BATCHSZ];
__device__ float g_squ[INIT_BLOCKS];
__device__ float g_sqi[INIT_BLOCKS];
__device__ int   g_bsum[2 * SNB];
__device__ int   g_bbase[2 * SNB];

// ---------------------------------------------------------------------------
// 1) total[0] = concat(user, item); per-block sum-of-squares partials
// ---------------------------------------------------------------------------
__global__ __launch_bounds__(256) void init_kernel(const float4* __restrict__ ue,
                                                   const float4* __restrict__ ie) {
    __shared__ float shu[256], shi[256];
    int i = blockIdx.x * 256 + threadIdx.x;
    const int tot4 = NN * DD / 4;
    const int nu4  = NU * DD / 4;
    float su = 0.f, si = 0.f;
    if (i < tot4) {
        float4 v;
        if (i < nu4) { v = ue[i]; su = v.x*v.x + v.y*v.y + v.z*v.z + v.w*v.w; }
        else         { v = ie[i - nu4]; si = v.x*v.x + v.y*v.y + v.z*v.z + v.w*v.w; }
        ((float4*)g_total[0])[i] = v;
    }
    shu[threadIdx.x] = su; shi[threadIdx.x] = si;
    __syncthreads();
    for (int s = 128; s; s >>= 1) {
        if (threadIdx.x < s) {
            shu[threadIdx.x] += shu[threadIdx.x + s];
            shi[threadIdx.x] += shi[threadIdx.x + s];
        }
        __syncthreads();
    }
    if (threadIdx.x == 0) { g_squ[blockIdx.x] = shu[0]; g_sqi[blockIdx.x] = shi[0]; }
}

// ---------------------------------------------------------------------------
// 2) per-node norms for both behaviors + zero counters
// ---------------------------------------------------------------------------
__global__ __launch_bounds__(256) void norm_kernel(const float* __restrict__ oldd,
                                                   const float* __restrict__ nowd,
                                                   const float* __restrict__ dwp,
                                                   const float* __restrict__ owp) {
    int i = blockIdx.x * 256 + threadIdx.x;    // over [0, 2*NN)
    if (i >= 2 * NN) return;
    float dw = __ldg(dwp), ow = __ldg(owp);
    float od = __ldg(oldd + i), nd = __ldg(nowd + i);
    float den = sqrtf(fmaxf(od * dw, 0.f) + nd);
    float inv = 1.f / (den + EPSF);
    g_ns[i] = inv;
    g_rs[i] = sqrtf(fmaxf(od * ow, 0.f)) * inv;
    g_cnt[i] = 0;
}

// ---------------------------------------------------------------------------
// 3) histogram over dst (both behaviors)
// ---------------------------------------------------------------------------
__global__ __launch_bounds__(256) void hist_kernel(const int* __restrict__ dst_all) {
    int i = blockIdx.x * 256 + threadIdx.x;
    if (i >= 2 * NE) return;
    int b = (i >= NE);
    int d = __ldg(dst_all + i);
    atomicAdd(&g_cnt[b * NN + d], 1);
}

// ---------------------------------------------------------------------------
// 4a) chunk sums: 74 blocks, each sums SCHUNK counts
// ---------------------------------------------------------------------------
__global__ __launch_bounds__(256) void reduce_kernel() {
    __shared__ int sh[256];
    int blk = blockIdx.x;              // [0, 2*SNB)
    int b   = blk >= SNB;
    int c   = blk - b * SNB;
    const int* cnt = g_cnt + b * NN;
    int s = 0;
    int base = c * SCHUNK;
    #pragma unroll
    for (int k = 0; k < SCHUNK / 256; k++) {
        int i = base + k * 256 + threadIdx.x;
        if (i < NN) s += cnt[i];
    }
    sh[threadIdx.x] = s;
    __syncthreads();
    for (int st = 128; st; st >>= 1) {
        if (threadIdx.x < st) sh[threadIdx.x] += sh[threadIdx.x + st];
        __syncthreads();
    }
    if (threadIdx.x == 0) g_bsum[blk] = sh[0];
}

// ---------------------------------------------------------------------------
// 4b) scan the 37 partials per behavior (1 tiny block; 2 threads work)
// ---------------------------------------------------------------------------
__global__ void scanb_kernel() {
    int b = threadIdx.x;
    if (b < 2) {
        int run = 0;
        for (int i = 0; i < SNB; i++) {
            g_bbase[b * SNB + i] = run;
            run += g_bsum[b * SNB + i];
        }
        g_off[b * (NN + 1) + NN] = run;   // == NE
    }
}

// ---------------------------------------------------------------------------
// 4c) intra-chunk exclusive scan + base -> off, cur
// ---------------------------------------------------------------------------
__global__ __launch_bounds__(1024) void scanc_kernel() {
    int blk = blockIdx.x;              // [0, 2*SNB)
    int b   = blk >= SNB;
    int c   = blk - b * SNB;
    int tid = threadIdx.x, lane = tid & 31, wid = tid >> 5;
    __shared__ int wsum[32];

    const int* cnt = g_cnt + b * NN;
    int* off = g_off + b * (NN + 1);
    int* cur = g_cur + b * NN;

    int i0 = c * SCHUNK + tid * 4;
    int v0 = (i0 + 0 < NN) ? cnt[i0 + 0] : 0;
    int v1 = (i0 + 1 < NN) ? cnt[i0 + 1] : 0;
    int v2 = (i0 + 2 < NN) ? cnt[i0 + 2] : 0;
    int v3 = (i0 + 3 < NN) ? cnt[i0 + 3] : 0;
    int ts = v0 + v1 + v2 + v3;
    int x = ts;
    #pragma unroll
    for (int o = 1; o < 32; o <<= 1) { int y = __shfl_up_sync(~0u, x, o); if (lane >= o) x += y; }
    if (lane == 31) wsum[wid] = x;
    __syncthreads();
    if (wid == 0) {
        int w = wsum[lane];
        #pragma unroll
        for (int o = 1; o < 32; o <<= 1) { int y = __shfl_up_sync(~0u, w, o); if (lane >= o) w += y; }
        wsum[lane] = w;
    }
    __syncthreads();
    int excl = g_bbase[blk] + (x - ts) + (wid ? wsum[wid - 1] : 0);
    if (i0 + 0 < NN) { off[i0 + 0] = excl; cur[i0 + 0] = excl; } excl += v0;
    if (i0 + 1 < NN) { off[i0 + 1] = excl; cur[i0 + 1] = excl; } excl += v1;
    if (i0 + 2 < NN) { off[i0 + 2] = excl; cur[i0 + 2] = excl; } excl += v2;
    if (i0 + 3 < NN) { off[i0 + 3] = excl; cur[i0 + 3] = excl; }
}

// ---------------------------------------------------------------------------
// 5) CSR fill (both behaviors)
// ---------------------------------------------------------------------------
__global__ __launch_bounds__(256) void fill_kernel(const int* __restrict__ src_all,
                                                   const int* __restrict__ dst_all) {
    int i = blockIdx.x * 256 + threadIdx.x;
    if (i >= 2 * NE) return;
    int b = (i >= NE);
    int d = __ldg(dst_all + i);
    int s = __ldg(src_all + i);
    int pos = atomicAdd(&g_cur[b * NN + d], 1);
    g_csrc[b * NE + pos] = s;
}

// ---------------------------------------------------------------------------
// 6) fused gather + combine: one warp per node.
//    reads g_total[p], writes g_total[1-p].  (p resolved in DEVICE code)
// ---------------------------------------------------------------------------
__global__ __launch_bounds__(256) void gathcomb_kernel(
    const float* __restrict__ ls,     // last_stage[b] : [2][NN][DD]
    const float* __restrict__ cw,     // conv_w[b] : 4 floats
    int b, int p)
{
    int node = blockIdx.x * 8 + (threadIdx.x >> 5);
    if (node >= NN) return;
    int lane = threadIdx.x & 31;

    const float* tot_in  = g_total[p];
    float*       tot_out = g_total[1 - p];
    const int*   csrc    = g_csrc + (size_t)b * NE;
    const float* nsb     = g_ns + b * NN;

    int r0 = __ldg(g_off + b * (NN + 1) + node);
    int r1 = __ldg(g_off + b * (NN + 1) + node + 1);
    int cnt = r1 - r0;

    float ax = 0.f, ay = 0.f;
    for (int base = 0; base < cnt; base += 32) {
        int myidx = -1;
        if (base + lane < cnt) myidx = __ldg(csrc + r0 + base + lane);
        int m = min(32, cnt - base);
        #pragma unroll 4
        for (int k = 0; k < m; k++) {
            int s = __shfl_sync(0xffffffffu, myidx, k);
            float ns = __ldg(nsb + s);
            float2 v = *(const float2*)(tot_in + (size_t)s * DD + lane * 2);
            ax = fmaf(ns, v.x, ax);
            ay = fmaf(ns, v.y, ay);
        }
    }

    float inv = __ldg(g_ns + b * NN + node);
    float rs  = __ldg(g_rs + b * NN + node);
    float c00 = __ldg(cw + 0), c01 = __ldg(cw + 1);
    float c10 = __ldg(cw + 2), c11 = __ldg(cw + 3);

    size_t base2 = (size_t)node * DD + lane * 2;
    float2 t  = *(const float2*)(tot_in + base2);
    float2 l0 = *(const float2*)(ls + base2);
    float2 l1 = *(const float2*)(ls + (size_t)NN * DD + base2);

    float e1x = inv * ax, e1y = inv * ay;
    float mx = (t.x + (c00 * l0.x * rs + c01 * t.x) + (c10 * l1.x * rs + c11 * e1x)) * (1.f / 3.f);
    float my = (t.y + (c00 * l0.y * rs + c01 * t.y) + (c10 * l1.y * rs + c11 * e1y)) * (1.f / 3.f);

    float sq = mx * mx + my * my;
    #pragma unroll
    for (int o = 16; o; o >>= 1) sq += __shfl_xor_sync(0xffffffffu, sq, o);
    float rn = 1.f / fmaxf(sqrtf(sq), 1e-12f);

    float2 outv = make_float2(t.x + mx * rn, t.y + my * rn);
    *(float2*)(tot_out + base2) = outv;
}

// ---------------------------------------------------------------------------
// 7) BPR loss (one warp per sample); buffer chosen in device code
// ---------------------------------------------------------------------------
__global__ __launch_bounds__(256) void loss_kernel(const int* __restrict__ bdata,
                                                   int b, int which) {
    int w = (blockIdx.x * blockDim.x + threadIdx.x) >> 5;
    if (w >= BATCHSZ) return;
    int lane = threadIdx.x & 31;

    const float* emb = g_total[which];

    const int* r = bdata + (size_t)w * 6 + (size_t)b * 3;  // (BATCH, 2, 3)
    int u  = __ldg(r + 0);
    int pi = NU + __ldg(r + 1);
    int ni = NU + __ldg(r + 2);

    float2 uv = *(const float2*)(emb + (size_t)u  * DD + lane * 2);
    float2 pv = *(const float2*)(emb + (size_t)pi * DD + lane * 2);
    float2 nv = *(const float2*)(emb + (size_t)ni * DD + lane * 2);

    float s0 = uv.x * pv.x + uv.y * pv.y;
    float s1 = uv.x * nv.x + uv.y * nv.y;
    #pragma unroll
    for (int o = 16; o; o >>= 1) {
        s0 += __shfl_xor_sync(0xffffffffu, s0, o);
        s1 += __shfl_xor_sync(0xffffffffu, s1, o);
    }
    if (lane == 0) {
        float diff = s0 - s1;
        float sig  = 1.f / (1.f + expf(-diff));
        g_bpr[b * BATCHSZ + w] = -logf(GAMMAF + sig);
    }
}

// ---------------------------------------------------------------------------
// 8) final deterministic reduction -> out[0]
// ---------------------------------------------------------------------------
__global__ __launch_bounds__(1024) void final_kernel(float* __restrict__ out) {
    __shared__ float sh[1024];
    int t = threadIdx.x;

    float a = 0.f;
    for (int i = t; i < 2 * BATCHSZ; i += 1024) a += g_bpr[i];
    float su = 0.f, si = 0.f;
    for (int i = t; i < INIT_BLOCKS; i += 1024) { su += g_squ[i]; si += g_sqi[i]; }

    float res[3] = {a, su, si};
    float red[3];
    #pragma unroll
    for (int k = 0; k < 3; k++) {
        sh[t] = res[k];
        __syncthreads();
        for (int s = 512; s; s >>= 1) {
            if (t < s) sh[t] += sh[t + s];
            __syncthreads();
        }
        red[k] = sh[0];
        __syncthreads();
    }

    if (t == 0) {
        float total_loss = red[0] * (1.f / BATCHSZ);
        float emb_loss   = (sqrtf(red[1]) + sqrtf(red[2])) / (float)NI;
        out[0] = total_loss + 1e-4f * emb_loss;
    }
}

// ---------------------------------------------------------------------------
extern "C" void kernel_launch(void* const* d_in, const int* in_sizes, int n_in,
                              void* d_out, int out_size) {
    const float* ue    = (const float*)d_in[0];
    const float* ie    = (const float*)d_in[1];
    const float* nowd  = (const float*)d_in[2];
    const float* oldd  = (const float*)d_in[3];
    const float* ls    = (const float*)d_in[4];
    const float* dw    = (const float*)d_in[5];
    const float* ow    = (const float*)d_in[6];
    const float* cw    = (const float*)d_in[7];
    const int*   src   = (const int*)d_in[8];
    const int*   dst   = (const int*)d_in[9];
    const int*   bdata = (const int*)d_in[10];
    float*       out   = (float*)d_out;

    init_kernel<<<INIT_BLOCKS, 256>>>((const float4*)ue, (const float4*)ie);
    norm_kernel<<<(2 * NN + 255) / 256, 256>>>(oldd, nowd, dw, ow);
    hist_kernel<<<(2 * NE + 255) / 256, 256>>>(dst);
    reduce_kernel<<<2 * SNB, 256>>>();
    scanb_kernel<<<1, 32>>>();
    scanc_kernel<<<2 * SNB, 1024>>>();
    fill_kernel<<<(2 * NE + 255) / 256, 256>>>(src, dst);

    // behavior 0: read buf0 -> write buf1 ; behavior 1: read buf1 -> write buf0
    gathcomb_kernel<<<(NN + 7) / 8, 256>>>(ls, cw + 0, 0, 0);
    loss_kernel<<<(BATCHSZ * 32 + 255) / 256, 256>>>(bdata, 0, 1);
    gathcomb_kernel<<<(NN + 7) / 8, 256>>>(ls + (size_t)2 * NN * DD, cw + 4, 1, 1);
    loss_kernel<<<(BATCHSZ * 32 + 255) / 256, 256>>>(bdata, 1, 0);

    final_kernel<<<1, 1024>>>(out);
}

// round 8
// speedup vs baseline: 1.3464x; 1.0272x over previous
#include <cuda_runtime.h>
#include <cuda_bf16.h>

#define NU      50001
#define NI      100001
#define NN      150002
#define DD      64
#define NE      2000000
#define BATCHSZ 2048
#define EPSF    1e-9f
#define GAMMAF  1e-10f
#define INIT_BLOCKS 9376   // ceil(NN*DD/4 / 256)
#define NORM_ELEMS  (2 * NN)
#define SCHUNK  4096
#define SNB     37         // ceil(NN / SCHUNK)
#define GB      18751      // ceil(NN / 8)
#define LOSSB   256        // BATCHSZ warps / 8 warps per block

// ---------------- static scratch ----------------
__device__ __align__(128) float g_total[2][(size_t)NN * DD]; // ping-pong, 76.8 MB
__device__ int   g_cnt[2 * NN];
__device__ int   g_off[2 * (NN + 1)];
__device__ int   g_cur[2 * NN];
__device__ int   g_csrc[2 * NE];                             // CSR: src per slot
__device__ float g_ns[2 * NN];                               // 1/(den+eps)  (== norm)
__device__ float g_rs[2 * NN];                               // old_scale/(den+eps)
__device__ float g_bpr[2 * BATCHSZ];
__device__ float g_squ[INIT_BLOCKS];
__device__ float g_sqi[INIT_BLOCKS];
__device__ int   g_bsum[2 * SNB];
__device__ int   g_bbase[2 * SNB];

// ---------------------------------------------------------------------------
// 1) fused: total[0] = concat(user,item) + sumsq partials + per-node norms
//    (norm work is independent; first NORM blocks also handle one norm elem)
// ---------------------------------------------------------------------------
__global__ __launch_bounds__(256) void init_kernel(
    const float4* __restrict__ ue, const float4* __restrict__ ie,
    const float* __restrict__ oldd, const float* __restrict__ nowd,
    const float* __restrict__ dwp, const float* __restrict__ owp)
{
    __shared__ float shu[256], shi[256];
    int i = blockIdx.x * 256 + threadIdx.x;

    // ---- norm part (first 2*NN threads chip-wide) ----
    if (i < NORM_ELEMS) {
        float dw = __ldg(dwp), ow = __ldg(owp);
        float od = __ldg(oldd + i), nd = __ldg(nowd + i);
        float den = sqrtf(fmaxf(od * dw, 0.f) + nd);
        float inv = 1.f / (den + EPSF);
        g_ns[i] = inv;
        g_rs[i] = sqrtf(fmaxf(od * ow, 0.f)) * inv;
        g_cnt[i] = 0;
    }

    // ---- concat + sumsq part ----
    const int tot4 = NN * DD / 4;
    const int nu4  = NU * DD / 4;
    float su = 0.f, si = 0.f;
    if (i < tot4) {
        float4 v;
        if (i < nu4) { v = ue[i]; su = v.x*v.x + v.y*v.y + v.z*v.z + v.w*v.w; }
        else         { v = ie[i - nu4]; si = v.x*v.x + v.y*v.y + v.z*v.z + v.w*v.w; }
        ((float4*)g_total[0])[i] = v;
    }
    shu[threadIdx.x] = su; shi[threadIdx.x] = si;
    __syncthreads();
    for (int s = 128; s; s >>= 1) {
        if (threadIdx.x < s) {
            shu[threadIdx.x] += shu[threadIdx.x + s];
            shi[threadIdx.x] += shi[threadIdx.x + s];
        }
        __syncthreads();
    }
    if (threadIdx.x == 0) { g_squ[blockIdx.x] = shu[0]; g_sqi[blockIdx.x] = shi[0]; }
}

// ---------------------------------------------------------------------------
// 2) histogram over dst, int4-vectorized (4 edges/thread, both behaviors)
// ---------------------------------------------------------------------------
__global__ __launch_bounds__(256) void hist_kernel(const int4* __restrict__ dst4) {
    int i = blockIdx.x * 256 + threadIdx.x;      // [0, 2*NE/4)
    if (i >= 2 * NE / 4) return;
    int4 d = __ldg(dst4 + i);
    int* c = g_cnt + (i >= NE / 4 ? NN : 0);
    atomicAdd(c + d.x, 1);
    atomicAdd(c + d.y, 1);
    atomicAdd(c + d.z, 1);
    atomicAdd(c + d.w, 1);
}

// ---------------------------------------------------------------------------
// 3a) chunk sums
// ---------------------------------------------------------------------------
__global__ __launch_bounds__(256) void reduce_kernel() {
    __shared__ int sh[256];
    int blk = blockIdx.x;              // [0, 2*SNB)
    int b   = blk >= SNB;
    int c   = blk - b * SNB;
    const int* cnt = g_cnt + b * NN;
    int s = 0;
    int base = c * SCHUNK;
    #pragma unroll
    for (int k = 0; k < SCHUNK / 256; k++) {
        int i = base + k * 256 + threadIdx.x;
        if (i < NN) s += cnt[i];
    }
    sh[threadIdx.x] = s;
    __syncthreads();
    for (int st = 128; st; st >>= 1) {
        if (threadIdx.x < st) sh[threadIdx.x] += sh[threadIdx.x + st];
        __syncthreads();
    }
    if (threadIdx.x == 0) g_bsum[blk] = sh[0];
}

// ---------------------------------------------------------------------------
// 3b) scan the SNB partials per behavior
// ---------------------------------------------------------------------------
__global__ void scanb_kernel() {
    int b = threadIdx.x;
    if (b < 2) {
        int run = 0;
        for (int i = 0; i < SNB; i++) {
            g_bbase[b * SNB + i] = run;
            run += g_bsum[b * SNB + i];
        }
        g_off[b * (NN + 1) + NN] = run;   // == NE
    }
}

// ---------------------------------------------------------------------------
// 3c) intra-chunk exclusive scan + base -> off, cur
// ---------------------------------------------------------------------------
__global__ __launch_bounds__(1024) void scanc_kernel() {
    int blk = blockIdx.x;              // [0, 2*SNB)
    int b   = blk >= SNB;
    int c   = blk - b * SNB;
    int tid = threadIdx.x, lane = tid & 31, wid = tid >> 5;
    __shared__ int wsum[32];

    const int* cnt = g_cnt + b * NN;
    int* off = g_off + b * (NN + 1);
    int* cur = g_cur + b * NN;

    int i0 = c * SCHUNK + tid * 4;
    int v0 = (i0 + 0 < NN) ? cnt[i0 + 0] : 0;
    int v1 = (i0 + 1 < NN) ? cnt[i0 + 1] : 0;
    int v2 = (i0 + 2 < NN) ? cnt[i0 + 2] : 0;
    int v3 = (i0 + 3 < NN) ? cnt[i0 + 3] : 0;
    int ts = v0 + v1 + v2 + v3;
    int x = ts;
    #pragma unroll
    for (int o = 1; o < 32; o <<= 1) { int y = __shfl_up_sync(~0u, x, o); if (lane >= o) x += y; }
    if (lane == 31) wsum[wid] = x;
    __syncthreads();
    if (wid == 0) {
        int w = wsum[lane];
        #pragma unroll
        for (int o = 1; o < 32; o <<= 1) { int y = __shfl_up_sync(~0u, w, o); if (lane >= o) w += y; }
        wsum[lane] = w;
    }
    __syncthreads();
    int excl = g_bbase[blk] + (x - ts) + (wid ? wsum[wid - 1] : 0);
    if (i0 + 0 < NN) { off[i0 + 0] = excl; cur[i0 + 0] = excl; } excl += v0;
    if (i0 + 1 < NN) { off[i0 + 1] = excl; cur[i0 + 1] = excl; } excl += v1;
    if (i0 + 2 < NN) { off[i0 + 2] = excl; cur[i0 + 2] = excl; } excl += v2;
    if (i0 + 3 < NN) { off[i0 + 3] = excl; cur[i0 + 3] = excl; }
}

// ---------------------------------------------------------------------------
// 4) CSR fill, int4-vectorized (4 edges/thread, both behaviors)
// ---------------------------------------------------------------------------
__global__ __launch_bounds__(256) void fill_kernel(const int4* __restrict__ src4,
                                                   const int4* __restrict__ dst4) {
    int i = blockIdx.x * 256 + threadIdx.x;      // [0, 2*NE/4)
    if (i >= 2 * NE / 4) return;
    int b = (i >= NE / 4);
    int4 d = __ldg(dst4 + i);
    int4 s = __ldg(src4 + i);
    int* cur = g_cur + b * NN;
    int* csrc = g_csrc + (size_t)b * NE;
    csrc[atomicAdd(cur + d.x, 1)] = s.x;
    csrc[atomicAdd(cur + d.y, 1)] = s.y;
    csrc[atomicAdd(cur + d.z, 1)] = s.z;
    csrc[atomicAdd(cur + d.w, 1)] = s.w;
}

// ---------------------------------------------------------------------------
// device helper: BPR loss for one warp/sample
// ---------------------------------------------------------------------------
__device__ __forceinline__ void bpr_sample(const int* __restrict__ bdata,
                                           int b, int which, int w, int lane) {
    const float* emb = g_total[which];
    const int* r = bdata + (size_t)w * 6 + (size_t)b * 3;  // (BATCH, 2, 3)
    int u  = __ldg(r + 0);
    int pi = NU + __ldg(r + 1);
    int ni = NU + __ldg(r + 2);

    float2 uv = *(const float2*)(emb + (size_t)u  * DD + lane * 2);
    float2 pv = *(const float2*)(emb + (size_t)pi * DD + lane * 2);
    float2 nv = *(const float2*)(emb + (size_t)ni * DD + lane * 2);

    float s0 = uv.x * pv.x + uv.y * pv.y;
    float s1 = uv.x * nv.x + uv.y * nv.y;
    #pragma unroll
    for (int o = 16; o; o >>= 1) {
        s0 += __shfl_xor_sync(0xffffffffu, s0, o);
        s1 += __shfl_xor_sync(0xffffffffu, s1, o);
    }
    if (lane == 0) {
        float diff = s0 - s1;
        float sig  = 1.f / (1.f + expf(-diff));
        g_bpr[b * BATCHSZ + w] = -logf(GAMMAF + sig);
    }
}

// ---------------------------------------------------------------------------
// 5) fused gather + combine: one warp per node, float4 lanes, 2 edges/iter.
//    reads g_total[p], writes g_total[1-p].
//    Tail blocks (>= GB) compute BPR loss for behavior lb on buffer lwhich
//    (both read only already-written buffers).
// ---------------------------------------------------------------------------
__global__ __launch_bounds__(256) void gathcomb_kernel(
    const float* __restrict__ ls,     // last_stage[b] : [2][NN][DD]
    const float* __restrict__ cw,     // conv_w[b] : 4 floats
    int b, int p,
    const int* __restrict__ bdata, int lb, int lwhich)
{
    int lane = threadIdx.x & 31;
    if (blockIdx.x >= GB) {
        // ---- fused loss tail ----
        int w = (blockIdx.x - GB) * 8 + (threadIdx.x >> 5);
        if (w < BATCHSZ && lb >= 0) bpr_sample(bdata, lb, lwhich, w, lane);
        return;
    }

    int node = blockIdx.x * 8 + (threadIdx.x >> 5);
    if (node >= NN) return;
    int half = lane >> 4;      // 0 or 1: which edge of the pair
    int q    = lane & 15;      // float4 slot within row

    const float* tot_in  = g_total[p];
    float*       tot_out = g_total[1 - p];
    const int*   csrc    = g_csrc + (size_t)b * NE;
    const float* nsb     = g_ns + b * NN;

    int r0  = __ldg(g_off + b * (NN + 1) + node);
    int r1  = __ldg(g_off + b * (NN + 1) + node + 1);
    int cnt = r1 - r0;

    float4 acc = make_float4(0.f, 0.f, 0.f, 0.f);
    for (int base = 0; base < cnt; base += 32) {
        int mm = min(32, cnt - base);
        int myidx = 0; float myns = 0.f;
        if (base + lane < cnt) {
            myidx = __ldg(csrc + r0 + base + lane);
            myns  = __ldg(nsb + myidx);
        }
        int kend = mm & ~1;
        #pragma unroll 4
        for (int k = 0; k < kend; k += 2) {
            int   s = __shfl_sync(0xffffffffu, myidx, k + half);
            float w = __shfl_sync(0xffffffffu, myns,  k + half);
            float4 v = *(const float4*)(tot_in + (size_t)s * DD + q * 4);
            acc.x = fmaf(w, v.x, acc.x);
            acc.y = fmaf(w, v.y, acc.y);
            acc.z = fmaf(w, v.z, acc.z);
            acc.w = fmaf(w, v.w, acc.w);
        }
        if (mm & 1) {
            int   s = __shfl_sync(0xffffffffu, myidx, kend);
            float w = __shfl_sync(0xffffffffu, myns,  kend);
            if (half == 0) {
                float4 v = *(const float4*)(tot_in + (size_t)s * DD + q * 4);
                acc.x = fmaf(w, v.x, acc.x);
                acc.y = fmaf(w, v.y, acc.y);
                acc.z = fmaf(w, v.z, acc.z);
                acc.w = fmaf(w, v.w, acc.w);
            }
        }
    }
    // merge the two edge-halves: lanes l and l^16 cover the same features
    acc.x += __shfl_xor_sync(0xffffffffu, acc.x, 16);
    acc.y += __shfl_xor_sync(0xffffffffu, acc.y, 16);
    acc.z += __shfl_xor_sync(0xffffffffu, acc.z, 16);
    acc.w += __shfl_xor_sync(0xffffffffu, acc.w, 16);

    float inv = __ldg(g_ns + b * NN + node);
    float rs  = __ldg(g_rs + b * NN + node);
    float c00 = __ldg(cw + 0), c01 = __ldg(cw + 1);
    float c10 = __ldg(cw + 2), c11 = __ldg(cw + 3);

    size_t base4 = (size_t)node * DD + q * 4;
    float4 t  = *(const float4*)(tot_in + base4);
    float4 l0 = *(const float4*)(ls + base4);
    float4 l1 = *(const float4*)(ls + (size_t)NN * DD + base4);

    float4 m4;
    m4.x = (t.x + (c00 * l0.x * rs + c01 * t.x) + (c10 * l1.x * rs + c11 * (inv * acc.x))) * (1.f / 3.f);
    m4.y = (t.y + (c00 * l0.y * rs + c01 * t.y) + (c10 * l1.y * rs + c11 * (inv * acc.y))) * (1.f / 3.f);
    m4.z = (t.z + (c00 * l0.z * rs + c01 * t.z) + (c10 * l1.z * rs + c11 * (inv * acc.z))) * (1.f / 3.f);
    m4.w = (t.w + (c00 * l0.w * rs + c01 * t.w) + (c10 * l1.w * rs + c11 * (inv * acc.w))) * (1.f / 3.f);

    float sq = m4.x * m4.x + m4.y * m4.y + m4.z * m4.z + m4.w * m4.w;
    #pragma unroll
    for (int o = 8; o; o >>= 1) sq += __shfl_xor_sync(0xffffffffu, sq, o);  // 16-lane groups
    float rn = 1.f / fmaxf(sqrtf(sq), 1e-12f);

    if (half == 0) {
        float4 outv = make_float4(t.x + m4.x * rn, t.y + m4.y * rn,
                                  t.z + m4.z * rn, t.w + m4.w * rn);
        *(float4*)(tot_out + base4) = outv;
    }
}

// ---------------------------------------------------------------------------
// 6) standalone BPR loss (behavior 1)
// ---------------------------------------------------------------------------
__global__ __launch_bounds__(256) void loss_kernel(const int* __restrict__ bdata,
                                                   int b, int which) {
    int w = (blockIdx.x * blockDim.x + threadIdx.x) >> 5;
    if (w >= BATCHSZ) return;
    bpr_sample(bdata, b, which, w, threadIdx.x & 31);
}

// ---------------------------------------------------------------------------
// 7) final deterministic reduction -> out[0]
// ---------------------------------------------------------------------------
__global__ __launch_bounds__(1024) void final_kernel(float* __restrict__ out) {
    __shared__ float sh[1024];
    int t = threadIdx.x;

    float a = 0.f;
    for (int i = t; i < 2 * BATCHSZ; i += 1024) a += g_bpr[i];
    float su = 0.f, si = 0.f;
    for (int i = t; i < INIT_BLOCKS; i += 1024) { su += g_squ[i]; si += g_sqi[i]; }

    float res[3] = {a, su, si};
    float red[3];
    #pragma unroll
    for (int k = 0; k < 3; k++) {
        sh[t] = res[k];
        __syncthreads();
        for (int s = 512; s; s >>= 1) {
            if (t < s) sh[t] += sh[t + s];
            __syncthreads();
        }
        red[k] = sh[0];
        __syncthreads();
    }

    if (t == 0) {
        float total_loss = red[0] * (1.f / BATCHSZ);
        float emb_loss   = (sqrtf(red[1]) + sqrtf(red[2])) / (float)NI;
        out[0] = total_loss + 1e-4f * emb_loss;
    }
}

// ---------------------------------------------------------------------------
extern "C" void kernel_launch(void* const* d_in, const int* in_sizes, int n_in,
                              void* d_out, int out_size) {
    const float* ue    = (const float*)d_in[0];
    const float* ie    = (const float*)d_in[1];
    const float* nowd  = (const float*)d_in[2];
    const float* oldd  = (const float*)d_in[3];
    const float* ls    = (const float*)d_in[4];
    const float* dw    = (const float*)d_in[5];
    const float* ow    = (const float*)d_in[6];
    const float* cw    = (const float*)d_in[7];
    const int*   src   = (const int*)d_in[8];
    const int*   dst   = (const int*)d_in[9];
    const int*   bdata = (const int*)d_in[10];
    float*       out   = (float*)d_out;

    init_kernel<<<INIT_BLOCKS, 256>>>((const float4*)ue, (const float4*)ie,
                                      oldd, nowd, dw, ow);
    hist_kernel<<<(2 * NE / 4 + 255) / 256, 256>>>((const int4*)dst);
    reduce_kernel<<<2 * SNB, 256>>>();
    scanb_kernel<<<1, 32>>>();
    scanc_kernel<<<2 * SNB, 1024>>>();
    fill_kernel<<<(2 * NE / 4 + 255) / 256, 256>>>((const int4*)src, (const int4*)dst);

    // behavior 0: read buf0 -> write buf1 (no loss tail yet)
    gathcomb_kernel<<<GB, 256>>>(ls, cw + 0, 0, 0, bdata, -1, 0);
    // behavior 1: read buf1 -> write buf0 ; tail blocks run loss(b=0) on buf1
    gathcomb_kernel<<<GB + LOSSB, 256>>>(ls + (size_t)2 * NN * DD, cw + 4, 1, 1,
                                         bdata, 0, 1);
    loss_kernel<<<(BATCHSZ * 32 + 255) / 256, 256>>>(bdata, 1, 0);

    final_kernel<<<1, 1024>>>(out);
}